// round 8
// baseline (speedup 1.0000x reference)
#include <cuda_runtime.h>

#define KK     3
#define CIN    16
#define COUT   16
#define HH     64
#define WW     64
#define BB     4

#define TILE_H 4          // output rows per block
#define BX     64
#define BY     2          // 128 threads; each thread: 2 rows, 1 packed f-pair
#define PX     2
#define FG     2          // output channels per block
#define CHALF  8          // input channels per block (CIN split in 2)

#define SX_ROWS (TILE_H + 2)                 // 6
#define NOUT    (BB * COUT * HH * WW)        // 1,048,576

typedef unsigned long long ull;

// partial sums: [2][B][COUT][H][W]
__device__ float g_partial[2 * NOUT];

// ---------------- Blackwell packed f32x2 helpers ----------------
__device__ __forceinline__ ull pk2s(float v) {            // (v, v)
    ull r; asm("mov.b64 %0, {%1, %1};" : "=l"(r) : "f"(v)); return r;
}
__device__ __forceinline__ void upk2(ull v, float& lo, float& hi) {
    asm("mov.b64 {%0, %1}, %2;" : "=f"(lo), "=f"(hi) : "l"(v));
}
__device__ __forceinline__ ull pk2(float lo, float hi) {
    ull r; asm("mov.b64 %0, {%1, %2};" : "=l"(r) : "f"(lo), "f"(hi)); return r;
}
__device__ __forceinline__ ull ffma2(ull a, ull b, ull c) {
    ull d; asm("fma.rn.f32x2 %0, %1, %2, %3;" : "=l"(d) : "l"(a), "l"(b), "l"(c)); return d;
}
__device__ __forceinline__ ull fmul2(ull a, ull b) {
    ull d; asm("mul.rn.f32x2 %0, %1, %2;" : "=l"(d) : "l"(a), "l"(b)); return d;
}
__device__ __forceinline__ ull fadd2(ull a, ull b) {
    ull d; asm("add.rn.f32x2 %0, %1, %2;" : "=l"(d) : "l"(a), "l"(b)); return d;
}
__device__ __forceinline__ float frcp(float x) {
    float r; asm("rcp.approx.ftz.f32 %0, %1;" : "=f"(r) : "f"(x)); return r;
}

// Static SMEM (18.4 KB):
//  sC: packed coefficients, this block's f-pair x its 8 input channels:
//      per (c,p): 10 float2 (6 A-pairs, 4 B-pairs) -> 720 float2 = 5760 B
//  sX: 8 input-channel tiles, 6 rows x 66 cols = 12672 B
__global__ __launch_bounds__(BX * BY)
void kaconv_kernel(const float* __restrict__ x,
                   const float* __restrict__ A,
                   const float* __restrict__ Bc) {
    __shared__ __align__(16) ull  sC[CHALF * 9 * 10];  // 720 slots = 5760 B
    __shared__ float              sX[CHALF * SX_ROWS * 66];

    const int tx  = threadIdx.x;
    const int ty  = threadIdx.y;
    const int tid = ty * BX + tx;
    const int h0  = blockIdx.x * TILE_H;
    const int b   = blockIdx.y;
    const int f0  = (blockIdx.z >> 1) * FG;
    const int ch  = blockIdx.z & 1;            // which c-half
    const int c0  = ch * CHALF;

    // ---- stage packed coefficients for channels c0..c0+7 ----
    float2* sCf = reinterpret_cast<float2*>(sC);
    for (int i = tid; i < CHALF * 9 * 10; i += BX * BY) {
        int ii = i;
        const int k = ii % 10; ii /= 10;
        const int p = ii % 9;
        const int c = c0 + ii / 9;
        float lo, hi;
        if (k < 6) {
            lo = A[(( f0      * CIN + c) * 9 + p) * 6 + k];
            hi = A[(((f0 + 1) * CIN + c) * 9 + p) * 6 + k];
        } else {
            const int j = k - 6;
            lo = Bc[(( f0      * CIN + c) * 9 + p) * 4 + j];
            hi = Bc[(((f0 + 1) * CIN + c) * 9 + p) * 4 + j];
        }
        sCf[i] = make_float2(lo, hi);
    }

    // ---- stage 8 input-channel tiles with zero-padded halo ----
    for (int i = tid; i < CHALF * SX_ROWS * 66; i += BX * BY) {
        const int col = i % 66;
        const int r   = (i / 66) % SX_ROWS;
        const int cl  = i / (66 * SX_ROWS);
        const int gh  = h0 + r - 1;
        const int gw  = col - 1;
        float v = 0.0f;
        if (gh >= 0 && gh < HH && gw >= 0 && gw < WW)
            v = x[((b * CIN + c0 + cl) * HH + gh) * WW + gw];
        sX[(cl * SX_ROWS + r) * 66 + col] = v;
    }
    __syncthreads();

    const ulonglong2* sC2 = reinterpret_cast<const ulonglong2*>(sC);

    ull acc0 = 0ull, acc1 = 0ull;

    #pragma unroll 1
    for (int c = 0; c < CHALF; c++) {
        // 4 rows x 3 cols register window covers both pixels' 3x3 windows
        float xr[PX + 2][3];
        #pragma unroll
        for (int r = 0; r < PX + 2; r++)
            #pragma unroll
            for (int j = 0; j < 3; j++)
                xr[r][j] = sX[(c * SX_ROWS + PX * ty + r) * 66 + (tx + j)];

        const ulonglong2* pc = sC2 + c * 45;   // 5 ulonglong2 per (c,p)
        #pragma unroll
        for (int p = 0; p < 9; p++) {
            const int di = p / 3, dj = p % 3;
            const ulonglong2 u0 = pc[p * 5 + 0];  // {A0, A1}
            const ulonglong2 u1 = pc[p * 5 + 1];  // {A2, A3}
            const ulonglong2 u2 = pc[p * 5 + 2];  // {A4, A5}
            const ulonglong2 u3 = pc[p * 5 + 3];  // {B1, B2}
            const ulonglong2 u4 = pc[p * 5 + 4];  // {B3, B4}

            #pragma unroll
            for (int py = 0; py < PX; py++) {
                const ull X = pk2s(xr[py + di][dj]);

                // P = a0 + ... + a5 x^5 (Horner, packed over f-pair)
                ull P = ffma2(u2.y, X, u2.x);
                P = ffma2(P, X, u1.y);
                P = ffma2(P, X, u1.x);
                P = ffma2(P, X, u0.y);
                P = ffma2(P, X, u0.x);

                // S = x*(b1 + x*(b2 + x*(b3 + x*b4)))
                ull T = ffma2(u4.y, X, u4.x);
                T = ffma2(T, X, u3.y);
                T = ffma2(T, X, u3.x);
                T = fmul2(T, X);

                // Q = 1 + |S|; R = 1/Q
                float t0, t1; upk2(T, t0, t1);
                const ull R = pk2(frcp(1.0f + fabsf(t0)), frcp(1.0f + fabsf(t1)));

                if (py == 0) acc0 = ffma2(P, R, acc0);
                else         acc1 = ffma2(P, R, acc1);
            }
        }
    }

    // ---- write partials: 2 pixels x 2 channels ----
    const int hA = h0 + PX * ty;
    const int w  = tx;
    float a0, a1, b0, b1;
    upk2(acc0, a0, a1);
    upk2(acc1, b0, b1);
    float* op = g_partial + ch * NOUT + ((b * COUT + f0) * HH + hA) * WW + w;
    op[0]                = a0;
    op[WW]               = b0;
    op[HH * WW]          = a1;
    op[HH * WW + WW]     = b1;
}

// ---- combine: out = partial[0] + partial[1] ----
// One float4 per thread: 262144 threads, fully latency-tolerant.
__global__ __launch_bounds__(128)
void combine_kernel(float* __restrict__ out) {
    const int i = blockIdx.x * 128 + threadIdx.x;       // float4 index
    const float4 a = reinterpret_cast<const float4*>(g_partial)[i];
    const float4 b = reinterpret_cast<const float4*>(g_partial + NOUT)[i];
    float4 r;
    r.x = a.x + b.x; r.y = a.y + b.y; r.z = a.z + b.z; r.w = a.w + b.w;
    reinterpret_cast<float4*>(out)[i] = r;
}

extern "C" void kernel_launch(void* const* d_in, const int* in_sizes, int n_in,
                              void* d_out, int out_size) {
    const float* x  = (const float*)d_in[0];
    const float* A  = (const float*)d_in[1];
    const float* Bc = (const float*)d_in[2];
    float* out = (float*)d_out;

    dim3 grid(HH / TILE_H, BB, (COUT / FG) * 2);   // (16, 4, 16) = 1024 blocks
    dim3 block(BX, BY, 1);                          // 128 threads
    kaconv_kernel<<<grid, block>>>(x, A, Bc);

    combine_kernel<<<(NOUT / 4) / 128, 128>>>(out); // 2048 blocks x 128 thr
}